// round 15
// baseline (speedup 1.0000x reference)
#include <cuda_runtime.h>
#include <math.h>

// x: [B=16, nH=16, hd=64, H=64, W=64] fp32
#define NBATCH   16
#define ROWS_PB  1024        // nH*hd rows per batch
#define N_ROWS   16384
#define HW4      1024        // (H*W)/4 float4 per row
#define HD       64
#define LSEQ     16
#define BN       4

#define WORKERS  147
#define GRID     (WORKERS + 1)    // +1 tiny-math block; 148 <= 152 SMs
#define THREADS  1024
#define RPW      7                // max rows per worker block

__device__ float g_pooled[N_ROWS];
__device__ float g_delta[N_ROWS];
__device__ int   g_arrive[NBATCH];
__device__ volatile int g_flag[NBATCH];

// ---------------------------------------------------------------------------
__global__ void init_kernel()
{
    if (threadIdx.x < NBATCH) {
        g_arrive[threadIdx.x] = 0;
        g_flag[threadIdx.x] = 0;
    }
}

// ---------------------------------------------------------------------------
// Tiny per-batch math on warp 0: compress -> MHA(L=16,E=4,h=2) -> out_proj
// -> expand -> LN -> delta. Lane l (<16) = token l; lanes 16-31 shadow.
// ---------------------------------------------------------------------------
__device__ __forceinline__ void tiny_math(
    int b, const float* s_cw, const float* s_cb, const float* s_ipw,
    const float* s_ipb, const float* s_opw, const float* s_opb,
    const float* s_ew, const float* s_eb, const float* s_lnw,
    const float* s_lnb, float gv, int lane)
{
    const int l = lane & 15;
    const float* prow = g_pooled + b * ROWS_PB + l * HD;

    // compress
    float xc[BN];
    #pragma unroll
    for (int c = 0; c < BN; c++) xc[c] = s_cb[c];
    #pragma unroll
    for (int i = 0; i < HD; i++) {
        float p = prow[i];
        #pragma unroll
        for (int c = 0; c < BN; c++) xc[c] += p * s_cw[c * HD + i];
    }

    // qkv
    float qkv[12];
    #pragma unroll
    for (int r = 0; r < 12; r++) {
        float a = s_ipb[r];
        #pragma unroll
        for (int c = 0; c < BN; c++) a += s_ipw[r * BN + c] * xc[c];
        qkv[r] = a;
    }

    // attention (heads=2, dh=2); k/v exchanged via shuffles
    const float scale = 0.7071067811865475f;
    float o[BN];
    #pragma unroll
    for (int h = 0; h < 2; h++) {
        const float q0 = qkv[2*h], q1 = qkv[2*h + 1];
        const float myk0 = qkv[4 + 2*h], myk1 = qkv[5 + 2*h];
        const float myv0 = qkv[8 + 2*h], myv1 = qkv[9 + 2*h];
        float sc[LSEQ];
        float mx = -1e30f;
        #pragma unroll
        for (int j = 0; j < LSEQ; j++) {
            float kj0 = __shfl_sync(0xffffffffu, myk0, j);
            float kj1 = __shfl_sync(0xffffffffu, myk1, j);
            float s = (q0 * kj0 + q1 * kj1) * scale;
            sc[j] = s;
            mx = fmaxf(mx, s);
        }
        float den = 0.0f, o0 = 0.0f, o1 = 0.0f;
        #pragma unroll
        for (int j = 0; j < LSEQ; j++) {
            float e = __expf(sc[j] - mx);
            float vj0 = __shfl_sync(0xffffffffu, myv0, j);
            float vj1 = __shfl_sync(0xffffffffu, myv1, j);
            den += e;
            o0 += e * vj0;
            o1 += e * vj1;
        }
        float inv = 1.0f / den;
        o[2*h]     = o0 * inv;
        o[2*h + 1] = o1 * inv;
    }

    // out_proj
    float xa[BN];
    #pragma unroll
    for (int e = 0; e < BN; e++) {
        float a = s_opb[e];
        #pragma unroll
        for (int f = 0; f < BN; f++) a += s_opw[e * BN + f] * o[f];
        xa[e] = a;
    }

    // expand + residual + LN (recompute passes, low regs)
    float mu = 0.0f;
    #pragma unroll
    for (int i = 0; i < HD; i++) {
        float ex = s_eb[i];
        #pragma unroll
        for (int f = 0; f < BN; f++) ex += s_ew[i * BN + f] * xa[f];
        mu += prow[i] + gv * ex;
    }
    mu *= (1.0f / (float)HD);
    float var = 0.0f;
    #pragma unroll
    for (int i = 0; i < HD; i++) {
        float ex = s_eb[i];
        #pragma unroll
        for (int f = 0; f < BN; f++) ex += s_ew[i * BN + f] * xa[f];
        float d = (prow[i] + gv * ex) - mu;
        var += d * d;
    }
    var *= (1.0f / (float)HD);
    float inv = rsqrtf(var + 1e-5f);
    #pragma unroll
    for (int i = 0; i < HD; i++) {
        float ex = s_eb[i];
        #pragma unroll
        for (int f = 0; f < BN; f++) ex += s_ew[i * BN + f] * xa[f];
        float pv = prow[i];
        float y = pv + gv * ex;
        float outv = (y - mu) * inv * s_lnw[i] + s_lnb[i];
        if (lane < 16)
            g_delta[b * ROWS_PB + l * HD + i] = outv - pv;
    }
}

// ---------------------------------------------------------------------------
// Fused pipelined kernel.
//   Worker blocks (0..146): pool(0); for b: [pool(b+1)], wait flag[b], add(b).
//   Tiny block (147): for b: wait arrive[b]==147, tiny_math(b), flag[b]=1.
// Worker's add(b) re-reads the slab it pooled one phase earlier -> L2/L1 hits.
// ---------------------------------------------------------------------------
__global__ void __launch_bounds__(THREADS, 1) fused_kernel(
    const float4* __restrict__ x, float4* __restrict__ out,
    const float* __restrict__ cw,  const float* __restrict__ cb,
    const float* __restrict__ ipw, const float* __restrict__ ipb,
    const float* __restrict__ opw, const float* __restrict__ opb,
    const float* __restrict__ ew,  const float* __restrict__ eb,
    const float* __restrict__ lnw, const float* __restrict__ lnb,
    const float* __restrict__ gate)
{
    const int bid = blockIdx.x;
    const int tid = threadIdx.x;
    const int lane = tid & 31;
    const int warp = tid >> 5;

    if (bid == WORKERS) {
        // ================= TINY-MATH BLOCK =================
        __shared__ float s_cw[BN * HD], s_cb[BN];
        __shared__ float s_ipw[12 * BN], s_ipb[12];
        __shared__ float s_opw[BN * BN], s_opb[BN];
        __shared__ float s_ew[HD * BN], s_eb[HD];
        __shared__ float s_lnw[HD], s_lnb[HD];
        __shared__ float s_gate;

        if (tid < BN * HD) s_cw[tid] = cw[tid];
        if (tid < BN)       s_cb[tid] = cb[tid];
        if (tid < 12 * BN)  s_ipw[tid] = ipw[tid];
        if (tid < 12)       s_ipb[tid] = ipb[tid];
        if (tid < BN * BN)  s_opw[tid] = opw[tid];
        if (tid >= 32 && tid < 32 + BN) s_opb[tid - 32] = opb[tid - 32];
        if (tid >= 256 && tid < 256 + HD * BN) s_ew[tid - 256] = ew[tid - 256];
        if (tid >= 512 && tid < 512 + HD) s_eb[tid - 512] = eb[tid - 512];
        if (tid >= 576 && tid < 576 + HD) s_lnw[tid - 576] = lnw[tid - 576];
        if (tid >= 640 && tid < 640 + HD) s_lnb[tid - 640] = lnb[tid - 640];
        if (tid == 704) s_gate = gate[0];
        __syncthreads();

        if (warp == 0) {
            for (int b = 0; b < NBATCH; b++) {
                if (lane == 0) {
                    while (((volatile int*)g_arrive)[b] < WORKERS)
                        __nanosleep(32);
                }
                __syncwarp();
                __threadfence();   // acquire: workers' pooled writes
                tiny_math(b, s_cw, s_cb, s_ipw, s_ipb, s_opw, s_opb,
                          s_ew, s_eb, s_lnw, s_lnb, s_gate, lane);
                __threadfence();   // release delta before flag
                if (lane == 0) g_flag[b] = 1;
            }
        }
        return;
    }

    // ================= WORKER BLOCKS =================
    __shared__ float s_red[RPW * 32];

    // --- pool one batch: block reduces rows {bid + k*147 | k, r < 1024} ---
    auto pool = [&](int b) {
        float4 v[RPW];
        #pragma unroll
        for (int k = 0; k < RPW; k++) {
            int r = bid + k * WORKERS;
            if (r < ROWS_PB)
                v[k] = x[((size_t)(b * ROWS_PB + r)) * HW4 + tid];
        }
        #pragma unroll
        for (int k = 0; k < RPW; k++) {
            int r = bid + k * WORKERS;
            if (r < ROWS_PB) {
                float s = (v[k].x + v[k].y) + (v[k].z + v[k].w);
                #pragma unroll
                for (int off = 16; off > 0; off >>= 1)
                    s += __shfl_down_sync(0xffffffffu, s, off);
                if (lane == 0) s_red[k * 32 + warp] = s;
            }
        }
        __syncthreads();
        if (warp < RPW) {
            int r = bid + warp * WORKERS;
            if (r < ROWS_PB) {
                float s = s_red[warp * 32 + lane];
                #pragma unroll
                for (int off = 16; off > 0; off >>= 1)
                    s += __shfl_down_sync(0xffffffffu, s, off);
                if (lane == 0) {
                    g_pooled[b * ROWS_PB + r] = s * (1.0f / 4096.0f);
                    __threadfence();   // publish before arrive
                }
            }
        }
        __syncthreads();
        if (tid == 0) atomicAdd(&g_arrive[b], 1);
        __syncthreads();   // keep s_red safe for reuse next batch
    };

    pool(0);

    for (int b = 0; b < NBATCH; b++) {
        if (b + 1 < NBATCH) pool(b + 1);   // overlaps tiny_math(b)

        if (tid == 0) {
            while (g_flag[b] == 0) __nanosleep(32);
        }
        __syncthreads();   // ordering: flag observed before delta/x reads

        // --- add: same rows this block pooled (L2/L1 resident) ---
        float4 v[RPW];
        float  dl[RPW];
        #pragma unroll
        for (int k = 0; k < RPW; k++) {
            int r = bid + k * WORKERS;
            if (r < ROWS_PB) {
                int row = b * ROWS_PB + r;
                dl[k] = g_delta[row];
                v[k]  = x[(size_t)row * HW4 + tid];
            }
        }
        #pragma unroll
        for (int k = 0; k < RPW; k++) {
            int r = bid + k * WORKERS;
            if (r < ROWS_PB) {
                int row = b * ROWS_PB + r;
                float4 w = v[k];
                float d = dl[k];
                w.x += d; w.y += d; w.z += d; w.w += d;
                __stcs(out + (size_t)row * HW4 + tid, w);
            }
        }
    }
}

// ---------------------------------------------------------------------------
extern "C" void kernel_launch(void* const* d_in, const int* in_sizes, int n_in,
                              void* d_out, int out_size)
{
    const float* x   = (const float*)d_in[0];
    const float* cw  = (const float*)d_in[1];
    const float* cb  = (const float*)d_in[2];
    const float* ipw = (const float*)d_in[3];
    const float* ipb = (const float*)d_in[4];
    const float* opw = (const float*)d_in[5];
    const float* opb = (const float*)d_in[6];
    const float* ew  = (const float*)d_in[7];
    const float* eb  = (const float*)d_in[8];
    const float* lnw = (const float*)d_in[9];
    const float* lnb = (const float*)d_in[10];
    const float* gate= (const float*)d_in[11];
    float* out = (float*)d_out;

    init_kernel<<<1, 32>>>();
    fused_kernel<<<GRID, THREADS>>>((const float4*)x, (float4*)out,
                                    cw, cb, ipw, ipb, opw, opb,
                                    ew, eb, lnw, lnb, gate);
}

// round 16
// speedup vs baseline: 1.0210x; 1.0210x over previous
#include <cuda_runtime.h>
#include <math.h>

// x: [B=16, nH=16, hd=64, H=64, W=64] fp32
#define NBATCH   16
#define ROWS_PB  1024        // nH*hd rows per batch
#define N_ROWS   16384
#define HW4      1024        // (H*W)/4 float4 per row
#define HD       64
#define LSEQ     16
#define BN       4

#define WORKERS  147
#define GRID     (WORKERS + 1)    // +1 tiny-math block; 148 <= 152 SMs
#define THREADS  1024
#define RPW      7                // max rows per worker block

__device__ float g_pooled[N_ROWS];
__device__ float g_delta[N_ROWS];
__device__ int   g_arrive[NBATCH];
__device__ volatile int g_flag[NBATCH];

// ---------------------------------------------------------------------------
__global__ void init_kernel()
{
    if (threadIdx.x < NBATCH) {
        g_arrive[threadIdx.x] = 0;
        g_flag[threadIdx.x] = 0;
    }
}

// ---------------------------------------------------------------------------
// Tiny per-batch math on warp 0: compress -> MHA(L=16,E=4,h=2) -> out_proj
// -> expand -> LN -> delta. Lane l (<16) = token l; lanes 16-31 shadow.
// ---------------------------------------------------------------------------
__device__ __forceinline__ void tiny_math(
    int b, const float* s_cw, const float* s_cb, const float* s_ipw,
    const float* s_ipb, const float* s_opw, const float* s_opb,
    const float* s_ew, const float* s_eb, const float* s_lnw,
    const float* s_lnb, float gv, int lane)
{
    const int l = lane & 15;
    const float* prow = g_pooled + b * ROWS_PB + l * HD;

    // compress
    float xc[BN];
    #pragma unroll
    for (int c = 0; c < BN; c++) xc[c] = s_cb[c];
    #pragma unroll
    for (int i = 0; i < HD; i++) {
        float p = prow[i];
        #pragma unroll
        for (int c = 0; c < BN; c++) xc[c] += p * s_cw[c * HD + i];
    }

    // qkv
    float qkv[12];
    #pragma unroll
    for (int r = 0; r < 12; r++) {
        float a = s_ipb[r];
        #pragma unroll
        for (int c = 0; c < BN; c++) a += s_ipw[r * BN + c] * xc[c];
        qkv[r] = a;
    }

    // attention (heads=2, dh=2); k/v exchanged via shuffles
    const float scale = 0.7071067811865475f;
    float o[BN];
    #pragma unroll
    for (int h = 0; h < 2; h++) {
        const float q0 = qkv[2*h], q1 = qkv[2*h + 1];
        const float myk0 = qkv[4 + 2*h], myk1 = qkv[5 + 2*h];
        const float myv0 = qkv[8 + 2*h], myv1 = qkv[9 + 2*h];
        float sc[LSEQ];
        float mx = -1e30f;
        #pragma unroll
        for (int j = 0; j < LSEQ; j++) {
            float kj0 = __shfl_sync(0xffffffffu, myk0, j);
            float kj1 = __shfl_sync(0xffffffffu, myk1, j);
            float s = (q0 * kj0 + q1 * kj1) * scale;
            sc[j] = s;
            mx = fmaxf(mx, s);
        }
        float den = 0.0f, o0 = 0.0f, o1 = 0.0f;
        #pragma unroll
        for (int j = 0; j < LSEQ; j++) {
            float e = __expf(sc[j] - mx);
            float vj0 = __shfl_sync(0xffffffffu, myv0, j);
            float vj1 = __shfl_sync(0xffffffffu, myv1, j);
            den += e;
            o0 += e * vj0;
            o1 += e * vj1;
        }
        float inv = 1.0f / den;
        o[2*h]     = o0 * inv;
        o[2*h + 1] = o1 * inv;
    }

    // out_proj
    float xa[BN];
    #pragma unroll
    for (int e = 0; e < BN; e++) {
        float a = s_opb[e];
        #pragma unroll
        for (int f = 0; f < BN; f++) a += s_opw[e * BN + f] * o[f];
        xa[e] = a;
    }

    // expand + residual + LN (recompute passes, low regs)
    float mu = 0.0f;
    #pragma unroll
    for (int i = 0; i < HD; i++) {
        float ex = s_eb[i];
        #pragma unroll
        for (int f = 0; f < BN; f++) ex += s_ew[i * BN + f] * xa[f];
        mu += prow[i] + gv * ex;
    }
    mu *= (1.0f / (float)HD);
    float var = 0.0f;
    #pragma unroll
    for (int i = 0; i < HD; i++) {
        float ex = s_eb[i];
        #pragma unroll
        for (int f = 0; f < BN; f++) ex += s_ew[i * BN + f] * xa[f];
        float d = (prow[i] + gv * ex) - mu;
        var += d * d;
    }
    var *= (1.0f / (float)HD);
    float inv = rsqrtf(var + 1e-5f);
    #pragma unroll
    for (int i = 0; i < HD; i++) {
        float ex = s_eb[i];
        #pragma unroll
        for (int f = 0; f < BN; f++) ex += s_ew[i * BN + f] * xa[f];
        float pv = prow[i];
        float y = pv + gv * ex;
        float outv = (y - mu) * inv * s_lnw[i] + s_lnb[i];
        if (lane < 16)
            g_delta[b * ROWS_PB + l * HD + i] = outv - pv;
    }
}

// ---------------------------------------------------------------------------
// Fused pipelined kernel.
//   Worker blocks (0..146): pool(0); for b: [pool(b+1)], wait flag[b], add(b).
//   Tiny block (147): for b: wait arrive[b]==147, tiny_math(b), flag[b]=1.
// Worker's add(b) re-reads the slab it pooled one phase earlier -> L2/L1 hits.
// ---------------------------------------------------------------------------
__global__ void __launch_bounds__(THREADS, 1) fused_kernel(
    const float4* __restrict__ x, float4* __restrict__ out,
    const float* __restrict__ cw,  const float* __restrict__ cb,
    const float* __restrict__ ipw, const float* __restrict__ ipb,
    const float* __restrict__ opw, const float* __restrict__ opb,
    const float* __restrict__ ew,  const float* __restrict__ eb,
    const float* __restrict__ lnw, const float* __restrict__ lnb,
    const float* __restrict__ gate)
{
    const int bid = blockIdx.x;
    const int tid = threadIdx.x;
    const int lane = tid & 31;
    const int warp = tid >> 5;

    if (bid == WORKERS) {
        // ================= TINY-MATH BLOCK =================
        __shared__ float s_cw[BN * HD], s_cb[BN];
        __shared__ float s_ipw[12 * BN], s_ipb[12];
        __shared__ float s_opw[BN * BN], s_opb[BN];
        __shared__ float s_ew[HD * BN], s_eb[HD];
        __shared__ float s_lnw[HD], s_lnb[HD];
        __shared__ float s_gate;

        if (tid < BN * HD) s_cw[tid] = cw[tid];
        if (tid < BN)       s_cb[tid] = cb[tid];
        if (tid < 12 * BN)  s_ipw[tid] = ipw[tid];
        if (tid < 12)       s_ipb[tid] = ipb[tid];
        if (tid < BN * BN)  s_opw[tid] = opw[tid];
        if (tid >= 32 && tid < 32 + BN) s_opb[tid - 32] = opb[tid - 32];
        if (tid >= 256 && tid < 256 + HD * BN) s_ew[tid - 256] = ew[tid - 256];
        if (tid >= 512 && tid < 512 + HD) s_eb[tid - 512] = eb[tid - 512];
        if (tid >= 576 && tid < 576 + HD) s_lnw[tid - 576] = lnw[tid - 576];
        if (tid >= 640 && tid < 640 + HD) s_lnb[tid - 640] = lnb[tid - 640];
        if (tid == 704) s_gate = gate[0];
        __syncthreads();

        if (warp == 0) {
            for (int b = 0; b < NBATCH; b++) {
                if (lane == 0) {
                    while (((volatile int*)g_arrive)[b] < WORKERS)
                        __nanosleep(32);
                }
                __syncwarp();
                __threadfence();   // acquire: workers' pooled writes
                tiny_math(b, s_cw, s_cb, s_ipw, s_ipb, s_opw, s_opb,
                          s_ew, s_eb, s_lnw, s_lnb, s_gate, lane);
                __threadfence();   // release delta before flag
                if (lane == 0) g_flag[b] = 1;
            }
        }
        return;
    }

    // ================= WORKER BLOCKS =================
    __shared__ float s_red[RPW * 32];

    // --- pool one batch: block reduces rows {bid + k*147 | k, r < 1024} ---
    auto pool = [&](int b) {
        float4 v[RPW];
        #pragma unroll
        for (int k = 0; k < RPW; k++) {
            int r = bid + k * WORKERS;
            if (r < ROWS_PB)
                v[k] = x[((size_t)(b * ROWS_PB + r)) * HW4 + tid];
        }
        #pragma unroll
        for (int k = 0; k < RPW; k++) {
            int r = bid + k * WORKERS;
            if (r < ROWS_PB) {
                float s = (v[k].x + v[k].y) + (v[k].z + v[k].w);
                #pragma unroll
                for (int off = 16; off > 0; off >>= 1)
                    s += __shfl_down_sync(0xffffffffu, s, off);
                if (lane == 0) s_red[k * 32 + warp] = s;
            }
        }
        __syncthreads();
        if (warp < RPW) {
            int r = bid + warp * WORKERS;
            if (r < ROWS_PB) {
                float s = s_red[warp * 32 + lane];
                #pragma unroll
                for (int off = 16; off > 0; off >>= 1)
                    s += __shfl_down_sync(0xffffffffu, s, off);
                if (lane == 0) {
                    g_pooled[b * ROWS_PB + r] = s * (1.0f / 4096.0f);
                    __threadfence();   // publish before arrive
                }
            }
        }
        __syncthreads();
        if (tid == 0) atomicAdd(&g_arrive[b], 1);
        __syncthreads();   // keep s_red safe for reuse next batch
    };

    pool(0);

    for (int b = 0; b < NBATCH; b++) {
        if (b + 1 < NBATCH) pool(b + 1);   // overlaps tiny_math(b)

        if (tid == 0) {
            while (g_flag[b] == 0) __nanosleep(32);
        }
        __syncthreads();   // ordering: flag observed before delta/x reads

        // --- add: same rows this block pooled (L2/L1 resident) ---
        float4 v[RPW];
        float  dl[RPW];
        #pragma unroll
        for (int k = 0; k < RPW; k++) {
            int r = bid + k * WORKERS;
            if (r < ROWS_PB) {
                int row = b * ROWS_PB + r;
                dl[k] = g_delta[row];
                v[k]  = x[(size_t)row * HW4 + tid];
            }
        }
        #pragma unroll
        for (int k = 0; k < RPW; k++) {
            int r = bid + k * WORKERS;
            if (r < ROWS_PB) {
                int row = b * ROWS_PB + r;
                float4 w = v[k];
                float d = dl[k];
                w.x += d; w.y += d; w.z += d; w.w += d;
                __stcs(out + (size_t)row * HW4 + tid, w);
            }
        }
    }
}

// ---------------------------------------------------------------------------
extern "C" void kernel_launch(void* const* d_in, const int* in_sizes, int n_in,
                              void* d_out, int out_size)
{
    const float* x   = (const float*)d_in[0];
    const float* cw  = (const float*)d_in[1];
    const float* cb  = (const float*)d_in[2];
    const float* ipw = (const float*)d_in[3];
    const float* ipb = (const float*)d_in[4];
    const float* opw = (const float*)d_in[5];
    const float* opb = (const float*)d_in[6];
    const float* ew  = (const float*)d_in[7];
    const float* eb  = (const float*)d_in[8];
    const float* lnw = (const float*)d_in[9];
    const float* lnb = (const float*)d_in[10];
    const float* gate= (const float*)d_in[11];
    float* out = (float*)d_out;

    init_kernel<<<1, 32>>>();
    fused_kernel<<<GRID, THREADS>>>((const float4*)x, (float4*)out,
                                    cw, cb, ipw, ipb, opw, opb,
                                    ew, eb, lnw, lnb, gate);
}

// round 17
// speedup vs baseline: 1.0245x; 1.0035x over previous
#include <cuda_runtime.h>
#include <math.h>

// x: [B=16, nH=16, hd=64, H=64, W=64] fp32
#define NBATCH   16
#define ROWS_PB  1024        // nH*hd rows per batch
#define N_ROWS   16384
#define HW4      1024        // (H*W)/4 float4 per row
#define HD       64
#define LSEQ     16
#define BN       4

#define WORKERS  147
#define GRID     (WORKERS + 1)    // +1 tiny-math block; 148 <= 152 SMs
#define THREADS  1024
#define RPW      7                // max rows per worker block

__device__ float g_pooled[N_ROWS];
__device__ float g_delta[N_ROWS];
__device__ int   g_arrive[NBATCH];
__device__ volatile int g_flag[NBATCH];

// ---------------------------------------------------------------------------
__global__ void init_kernel()
{
    if (threadIdx.x < NBATCH) {
        g_arrive[threadIdx.x] = 0;
        g_flag[threadIdx.x] = 0;
    }
}

// ---------------------------------------------------------------------------
// Tiny per-batch math on warp 0: compress -> MHA(L=16,E=4,h=2) -> out_proj
// -> expand -> LN -> delta. Lane l (<16) = token l; lanes 16-31 shadow.
// ---------------------------------------------------------------------------
__device__ __forceinline__ void tiny_math(
    int b, const float* s_cw, const float* s_cb, const float* s_ipw,
    const float* s_ipb, const float* s_opw, const float* s_opb,
    const float* s_ew, const float* s_eb, const float* s_lnw,
    const float* s_lnb, float gv, int lane)
{
    const int l = lane & 15;
    const float* prow = g_pooled + b * ROWS_PB + l * HD;

    // compress
    float xc[BN];
    #pragma unroll
    for (int c = 0; c < BN; c++) xc[c] = s_cb[c];
    #pragma unroll
    for (int i = 0; i < HD; i++) {
        float p = prow[i];
        #pragma unroll
        for (int c = 0; c < BN; c++) xc[c] += p * s_cw[c * HD + i];
    }

    // qkv
    float qkv[12];
    #pragma unroll
    for (int r = 0; r < 12; r++) {
        float a = s_ipb[r];
        #pragma unroll
        for (int c = 0; c < BN; c++) a += s_ipw[r * BN + c] * xc[c];
        qkv[r] = a;
    }

    // attention (heads=2, dh=2); k/v exchanged via shuffles
    const float scale = 0.7071067811865475f;
    float o[BN];
    #pragma unroll
    for (int h = 0; h < 2; h++) {
        const float q0 = qkv[2*h], q1 = qkv[2*h + 1];
        const float myk0 = qkv[4 + 2*h], myk1 = qkv[5 + 2*h];
        const float myv0 = qkv[8 + 2*h], myv1 = qkv[9 + 2*h];
        float sc[LSEQ];
        float mx = -1e30f;
        #pragma unroll
        for (int j = 0; j < LSEQ; j++) {
            float kj0 = __shfl_sync(0xffffffffu, myk0, j);
            float kj1 = __shfl_sync(0xffffffffu, myk1, j);
            float s = (q0 * kj0 + q1 * kj1) * scale;
            sc[j] = s;
            mx = fmaxf(mx, s);
        }
        float den = 0.0f, o0 = 0.0f, o1 = 0.0f;
        #pragma unroll
        for (int j = 0; j < LSEQ; j++) {
            float e = __expf(sc[j] - mx);
            float vj0 = __shfl_sync(0xffffffffu, myv0, j);
            float vj1 = __shfl_sync(0xffffffffu, myv1, j);
            den += e;
            o0 += e * vj0;
            o1 += e * vj1;
        }
        float inv = 1.0f / den;
        o[2*h]     = o0 * inv;
        o[2*h + 1] = o1 * inv;
    }

    // out_proj
    float xa[BN];
    #pragma unroll
    for (int e = 0; e < BN; e++) {
        float a = s_opb[e];
        #pragma unroll
        for (int f = 0; f < BN; f++) a += s_opw[e * BN + f] * o[f];
        xa[e] = a;
    }

    // expand + residual + LN (recompute passes, low regs)
    float mu = 0.0f;
    #pragma unroll
    for (int i = 0; i < HD; i++) {
        float ex = s_eb[i];
        #pragma unroll
        for (int f = 0; f < BN; f++) ex += s_ew[i * BN + f] * xa[f];
        mu += prow[i] + gv * ex;
    }
    mu *= (1.0f / (float)HD);
    float var = 0.0f;
    #pragma unroll
    for (int i = 0; i < HD; i++) {
        float ex = s_eb[i];
        #pragma unroll
        for (int f = 0; f < BN; f++) ex += s_ew[i * BN + f] * xa[f];
        float d = (prow[i] + gv * ex) - mu;
        var += d * d;
    }
    var *= (1.0f / (float)HD);
    float inv = rsqrtf(var + 1e-5f);
    #pragma unroll
    for (int i = 0; i < HD; i++) {
        float ex = s_eb[i];
        #pragma unroll
        for (int f = 0; f < BN; f++) ex += s_ew[i * BN + f] * xa[f];
        float pv = prow[i];
        float y = pv + gv * ex;
        float outv = (y - mu) * inv * s_lnw[i] + s_lnb[i];
        if (lane < 16)
            g_delta[b * ROWS_PB + l * HD + i] = outv - pv;
    }
}

// ---------------------------------------------------------------------------
// Fused pipelined kernel.
//   Worker blocks (0..146): pool(0); for b: [pool(b+1)], wait flag[b], add(b).
//   Tiny block (147): for b: wait arrive[b]==147, tiny_math(b), flag[b]=1.
// Worker's add(b) re-reads the slab it pooled one phase earlier -> L2/L1 hits.
// ---------------------------------------------------------------------------
__global__ void __launch_bounds__(THREADS, 1) fused_kernel(
    const float4* __restrict__ x, float4* __restrict__ out,
    const float* __restrict__ cw,  const float* __restrict__ cb,
    const float* __restrict__ ipw, const float* __restrict__ ipb,
    const float* __restrict__ opw, const float* __restrict__ opb,
    const float* __restrict__ ew,  const float* __restrict__ eb,
    const float* __restrict__ lnw, const float* __restrict__ lnb,
    const float* __restrict__ gate)
{
    const int bid = blockIdx.x;
    const int tid = threadIdx.x;
    const int lane = tid & 31;
    const int warp = tid >> 5;

    if (bid == WORKERS) {
        // ================= TINY-MATH BLOCK =================
        __shared__ float s_cw[BN * HD], s_cb[BN];
        __shared__ float s_ipw[12 * BN], s_ipb[12];
        __shared__ float s_opw[BN * BN], s_opb[BN];
        __shared__ float s_ew[HD * BN], s_eb[HD];
        __shared__ float s_lnw[HD], s_lnb[HD];
        __shared__ float s_gate;

        if (tid < BN * HD) s_cw[tid] = cw[tid];
        if (tid < BN)       s_cb[tid] = cb[tid];
        if (tid < 12 * BN)  s_ipw[tid] = ipw[tid];
        if (tid < 12)       s_ipb[tid] = ipb[tid];
        if (tid < BN * BN)  s_opw[tid] = opw[tid];
        if (tid >= 32 && tid < 32 + BN) s_opb[tid - 32] = opb[tid - 32];
        if (tid >= 256 && tid < 256 + HD * BN) s_ew[tid - 256] = ew[tid - 256];
        if (tid >= 512 && tid < 512 + HD) s_eb[tid - 512] = eb[tid - 512];
        if (tid >= 576 && tid < 576 + HD) s_lnw[tid - 576] = lnw[tid - 576];
        if (tid >= 640 && tid < 640 + HD) s_lnb[tid - 640] = lnb[tid - 640];
        if (tid == 704) s_gate = gate[0];
        __syncthreads();

        if (warp == 0) {
            for (int b = 0; b < NBATCH; b++) {
                if (lane == 0) {
                    while (((volatile int*)g_arrive)[b] < WORKERS)
                        __nanosleep(32);
                }
                __syncwarp();
                __threadfence();   // acquire: workers' pooled writes
                tiny_math(b, s_cw, s_cb, s_ipw, s_ipb, s_opw, s_opb,
                          s_ew, s_eb, s_lnw, s_lnb, s_gate, lane);
                __threadfence();   // release delta before flag
                if (lane == 0) g_flag[b] = 1;
            }
        }
        return;
    }

    // ================= WORKER BLOCKS =================
    __shared__ float s_red[RPW * 32];

    // --- pool one batch: block reduces rows {bid + k*147 | k, r < 1024} ---
    auto pool = [&](int b) {
        float4 v[RPW];
        #pragma unroll
        for (int k = 0; k < RPW; k++) {
            int r = bid + k * WORKERS;
            if (r < ROWS_PB)
                v[k] = x[((size_t)(b * ROWS_PB + r)) * HW4 + tid];
        }
        #pragma unroll
        for (int k = 0; k < RPW; k++) {
            int r = bid + k * WORKERS;
            if (r < ROWS_PB) {
                float s = (v[k].x + v[k].y) + (v[k].z + v[k].w);
                #pragma unroll
                for (int off = 16; off > 0; off >>= 1)
                    s += __shfl_down_sync(0xffffffffu, s, off);
                if (lane == 0) s_red[k * 32 + warp] = s;
            }
        }
        __syncthreads();
        if (warp < RPW) {
            int r = bid + warp * WORKERS;
            if (r < ROWS_PB) {
                float s = s_red[warp * 32 + lane];
                #pragma unroll
                for (int off = 16; off > 0; off >>= 1)
                    s += __shfl_down_sync(0xffffffffu, s, off);
                if (lane == 0) {
                    g_pooled[b * ROWS_PB + r] = s * (1.0f / 4096.0f);
                    __threadfence();   // publish before arrive
                }
            }
        }
        __syncthreads();
        if (tid == 0) atomicAdd(&g_arrive[b], 1);
        __syncthreads();   // keep s_red safe for reuse next batch
    };

    pool(0);

    for (int b = 0; b < NBATCH; b++) {
        if (b + 1 < NBATCH) pool(b + 1);   // overlaps tiny_math(b)

        if (tid == 0) {
            while (g_flag[b] == 0) __nanosleep(32);
        }
        __syncthreads();   // ordering: flag observed before delta/x reads

        // --- add: same rows this block pooled (L2/L1 resident) ---
        float4 v[RPW];
        float  dl[RPW];
        #pragma unroll
        for (int k = 0; k < RPW; k++) {
            int r = bid + k * WORKERS;
            if (r < ROWS_PB) {
                int row = b * ROWS_PB + r;
                dl[k] = g_delta[row];
                v[k]  = x[(size_t)row * HW4 + tid];
            }
        }
        #pragma unroll
        for (int k = 0; k < RPW; k++) {
            int r = bid + k * WORKERS;
            if (r < ROWS_PB) {
                int row = b * ROWS_PB + r;
                float4 w = v[k];
                float d = dl[k];
                w.x += d; w.y += d; w.z += d; w.w += d;
                __stcs(out + (size_t)row * HW4 + tid, w);
            }
        }
    }
}

// ---------------------------------------------------------------------------
extern "C" void kernel_launch(void* const* d_in, const int* in_sizes, int n_in,
                              void* d_out, int out_size)
{
    const float* x   = (const float*)d_in[0];
    const float* cw  = (const float*)d_in[1];
    const float* cb  = (const float*)d_in[2];
    const float* ipw = (const float*)d_in[3];
    const float* ipb = (const float*)d_in[4];
    const float* opw = (const float*)d_in[5];
    const float* opb = (const float*)d_in[6];
    const float* ew  = (const float*)d_in[7];
    const float* eb  = (const float*)d_in[8];
    const float* lnw = (const float*)d_in[9];
    const float* lnb = (const float*)d_in[10];
    const float* gate= (const float*)d_in[11];
    float* out = (float*)d_out;

    init_kernel<<<1, 32>>>();
    fused_kernel<<<GRID, THREADS>>>((const float4*)x, (float4*)out,
                                    cw, cb, ipw, ipb, opw, opb,
                                    ew, eb, lnw, lnb, gate);
}